// round 2
// baseline (speedup 1.0000x reference)
#include <cuda_runtime.h>
#include <cstdint>

#define NH      128
#define NCODES  512
#define NCELLS  65536
#define NEDGES  (NCELLS + 1)
#define XMIN    (-5.75f)
#define XMAX    (5.75f)
#define CW      (11.5f / 65536.0f)
#define INV_CW  (65536.0f / 11.5f)
#define FULLM   0xffffffffu

__device__ __forceinline__ float neg_inf() { return __int_as_float(0xff800000); }
__device__ __forceinline__ float pos_inf() { return __int_as_float(0x7f800000); }

// -------- device scratch (no allocation allowed) --------
__device__ float g_ksort[NH];          // sorted kink positions (+inf padded)
__device__ int   g_actRank[NH];        // rank used for activity test (128 = special)
__device__ int   g_sgn[NH];            // +1: active when crossed, -1: active until crossed
__device__ float g_A[129 * NCODES];    // per-interval intercepts
__device__ float g_B[129 * NCODES];    // per-interval slopes
__device__ float g_score[NCODES];      // dec_w . emb[c]
__device__ float g_decb;
__device__ int   g_edgeArg[NEDGES];    // argmax at each grid edge
__device__ int   g_cellInfo[NCELLS];   // argmax | (bad<<31)

// -------- kernel 1: kinks, ranks, per-code decode score --------
__global__ void k_setup(const float* __restrict__ w1, const float* __restrict__ b1,
                        const float* __restrict__ emb, const float* __restrict__ dec_w,
                        const float* __restrict__ dec_b)
{
    __shared__ float sk[NH];
    int t = threadIdx.x;                 // 512 threads
    if (t < NH) {
        float w = w1[t], b = b1[t];
        sk[t] = (w != 0.0f) ? (-b / w) : pos_inf();
    }
    __syncthreads();
    if (t < NH) {
        float kv = sk[t];
        int r = 0;
        #pragma unroll 8
        for (int k = 0; k < NH; k++) {
            float o = sk[k];
            r += (o < kv) || (o == kv && k < t);   // unique rank via index tiebreak
        }
        g_ksort[r] = kv;
        float w = w1[t], b = b1[t];
        g_actRank[t] = (w != 0.0f) ? r : NH;       // w==0: never toggles
        g_sgn[t] = (w > 0.0f) ? 1 : ((w < 0.0f) ? -1 : ((b > 0.0f) ? -1 : 1));
    }
    // score[c] = sum_d dec_w[d] * emb[c][d]
    float s = 0.0f;
    const float* er = emb + t * 256;
    for (int d = 0; d < 256; d++) s = fmaf(dec_w[d], er[d], s);
    g_score[t] = s;
    if (t == 0) g_decb = dec_b[0];
}

// -------- kernel 2: per-interval line coefficients (direct sums, no drift) --------
__global__ void k_ab(const float* __restrict__ w1, const float* __restrict__ b1,
                     const float* __restrict__ w2, const float* __restrict__ b2)
{
    __shared__ float sw[NH], sb[NH];
    __shared__ int   sR[NH], sS[NH];
    int t = threadIdx.x;                 // 512 threads = code c
    int i = blockIdx.x;                  // interval 0..128
    if (t < NH) { sw[t] = w1[t]; sb[t] = b1[t]; sR[t] = g_actRank[t]; sS[t] = g_sgn[t]; }
    __syncthreads();
    float A = b2[t], Bv = 0.0f;
    const float* wr = w2 + t * NH;
    for (int j = 0; j < NH; j++) {
        bool act = (sS[j] > 0) ? (sR[j] < i) : (sR[j] >= i);
        if (act) {                       // warp-uniform predicate (independent of c)
            float v = wr[j];
            A  = fmaf(v, sb[j], A);
            Bv = fmaf(v, sw[j], Bv);
        }
    }
    g_A[i * NCODES + t] = A;
    g_B[i * NCODES + t] = Bv;
}

__device__ __forceinline__ int find_interval(const float* sk, float x) {
    int lo = 0, hi = NH;
    #pragma unroll
    for (int it = 0; it < 8; it++) {
        if (lo < hi) {
            int mid = (lo + hi) >> 1;
            if (sk[mid] <= x) lo = mid + 1; else hi = mid;
        }
    }
    return lo;   // number of kinks <= x, in [0,128]
}

__device__ __forceinline__ void scan512(const float* __restrict__ Ar,
                                        const float* __restrict__ Br,
                                        float xv, int lane, int& out_idx)
{
    float best = neg_inf(); int bi = 0;
    #pragma unroll
    for (int k = 0; k < 16; k++) {
        int c = lane + (k << 5);
        float v = fmaf(Br[c], xv, Ar[c]);
        if (v > best) { best = v; bi = c; }        // ascending c -> first-max per lane
    }
    #pragma unroll
    for (int off = 16; off >= 1; off >>= 1) {
        float ov = __shfl_down_sync(FULLM, best, off);
        int   oi = __shfl_down_sync(FULLM, bi,  off);
        if (ov > best || (ov == best && oi < bi)) { best = ov; bi = oi; }
    }
    out_idx = __shfl_sync(FULLM, bi, 0);           // jnp.argmax first-index semantics
}

// -------- kernel 3: argmax at every grid edge (one warp per edge) --------
__global__ void k_edges()
{
    __shared__ float sk[NH];
    if (threadIdx.x < NH) sk[threadIdx.x] = g_ksort[threadIdx.x];
    __syncthreads();
    int e = blockIdx.x * 8 + (threadIdx.x >> 5);
    if (e >= NEDGES) return;
    int lane = threadIdx.x & 31;
    float xe = XMIN + (float)e * CW;
    int i = find_interval(sk, xe);
    int bi;
    scan512(g_A + i * NCODES, g_B + i * NCODES, xe, lane, bi);
    if (lane == 0) g_edgeArg[e] = bi;
}

// -------- kernel 4: classify cells (clean vs needs-fallback) --------
__global__ void k_cell()
{
    __shared__ float sk[NH];
    if (threadIdx.x < NH) sk[threadIdx.x] = g_ksort[threadIdx.x];
    __syncthreads();
    int g = blockIdx.x * blockDim.x + threadIdx.x;
    if (g >= NCELLS) return;
    int a0 = g_edgeArg[g], a1 = g_edgeArg[g + 1];
    bool bad = (a0 != a1);
    float xl = XMIN + (float)g * CW;
    #pragma unroll 8
    for (int j = 0; j < NH; j++) {       // flag cells containing (or adjacent to) a kink
        float kv = sk[j];
        bad |= (kv >= xl - CW) && (kv < xl + 2.0f * CW);
    }
    g_cellInfo[g] = a0 | (bad ? (int)0x80000000 : 0);
}

// -------- kernel 5: per-element lookup + rare warp-aggregated fallback --------
__global__ void k_main(const float* __restrict__ x_in, float* __restrict__ out,
                       int n, int write_idx)
{
    __shared__ float sk[NH];
    if (threadIdx.x < NH) sk[threadIdx.x] = g_ksort[threadIdx.x];
    __syncthreads();
    int b = blockIdx.x * blockDim.x + threadIdx.x;
    if (b >= n) return;
    float x = x_in[b];
    int iv = find_interval(sk, x);
    int idx = 0;
    bool need = true;
    if (x >= XMIN && x < XMAX) {
        int g = (int)((x - XMIN) * INV_CW);
        if (g >= NCELLS) g = NCELLS - 1;
        int info = g_cellInfo[g];
        idx = info & 0x7fffffff;
        need = (info < 0);
    }
    int lane = threadIdx.x & 31;
    unsigned mask = __ballot_sync(FULLM, need);
    while (mask) {                       // whole warp cooperates per fallback element
        int src = __ffs(mask) - 1; mask &= mask - 1;
        float xb = __shfl_sync(FULLM, x, src);
        int   ib = __shfl_sync(FULLM, iv, src);
        int bi;
        scan512(g_A + ib * NCODES, g_B + ib * NCODES, xb, lane, bi);
        if (lane == src) idx = bi;
    }
    out[b] = g_score[idx] + g_decb;
    if (write_idx) out[n + b] = (float)idx;
}

extern "C" void kernel_launch(void* const* d_in, const int* in_sizes, int n_in,
                              void* d_out, int out_size)
{
    const float* x     = (const float*)d_in[0];
    const float* w1    = (const float*)d_in[1];
    const float* b1    = (const float*)d_in[2];
    const float* w2    = (const float*)d_in[3];
    const float* b2    = (const float*)d_in[4];
    const float* emb   = (const float*)d_in[5];
    const float* dec_w = (const float*)d_in[6];
    const float* dec_b = (const float*)d_in[7];
    int n = in_sizes[0];
    float* out = (float*)d_out;

    k_setup<<<1, 512>>>(w1, b1, emb, dec_w, dec_b);
    k_ab<<<129, 512>>>(w1, b1, w2, b2);
    k_edges<<<(NEDGES + 7) / 8, 256>>>();
    k_cell<<<(NCELLS + 255) / 256, 256>>>();
    int write_idx = (out_size >= 2 * n) ? 1 : 0;
    k_main<<<(n + 255) / 256, 256>>>(x, out, n, write_idx);
}

// round 4
// speedup vs baseline: 2.0458x; 2.0458x over previous
#include <cuda_runtime.h>
#include <cstdint>

#define NH      128
#define NCODES  512
#define NCELLS  65536
#define NEDGES  (NCELLS + 1)
#define NEWARPS ((NEDGES + 15) / 16)          // 4097 warps, 16 edges each
#define XMIN    (-5.75f)
#define XMAX    (5.75f)
#define CW      (11.5f / 65536.0f)
#define INV_CW  (65536.0f / 11.5f)
#define FULLM   0xffffffffu

__device__ __forceinline__ float neg_inf() { return __int_as_float(0xff800000); }
__device__ __forceinline__ float pos_inf() { return __int_as_float(0x7f800000); }

// -------- device scratch (no allocation allowed) --------
__device__ float g_ksort[NH];           // sorted kink positions (+inf padded)
__device__ int   g_actRank[NH];         // rank for activity test (128 = never)
__device__ int   g_sgn[NH];
__device__ float g_A[129 * NCODES];     // per-interval intercepts
__device__ float g_B[129 * NCODES];     // per-interval slopes
__device__ float g_score[NCODES];       // dec_w . emb[c]
__device__ float g_decb;
__device__ int   g_edgeArg[NEDGES];
__device__ unsigned char g_kinkNear[NCELLS];  // set-only, deterministic per replay
__device__ int   g_cellInfo[NCELLS];    // argmax | (bad<<31)

// -------- kernel 1: kinks, ranks, signs, decoder bias --------
__global__ void k_setup(const float* __restrict__ w1, const float* __restrict__ b1,
                        const float* __restrict__ dec_b)
{
    __shared__ float sk[NH];
    int t = threadIdx.x;                 // 128 threads
    float w = w1[t], b = b1[t];
    sk[t] = (w != 0.0f) ? (-b / w) : pos_inf();
    __syncthreads();
    float kv = sk[t];
    int r = 0;
    #pragma unroll 8
    for (int k = 0; k < NH; k++) {
        float o = sk[k];
        r += (o < kv) || (o == kv && k < t);        // unique rank via index tiebreak
    }
    g_ksort[r] = kv;
    g_actRank[t] = (w != 0.0f) ? r : NH;
    g_sgn[t] = (w > 0.0f) ? 1 : ((w < 0.0f) ? -1 : ((b > 0.0f) ? -1 : 1));
    if (t == 0) g_decb = dec_b[0];
}

// -------- kernel 1b: score[c] = dec_w . emb[c], one warp per code --------
__global__ void k_score(const float* __restrict__ emb, const float* __restrict__ dec_w)
{
    int w = (blockIdx.x * blockDim.x + threadIdx.x) >> 5;   // code id, 512 warps
    int lane = threadIdx.x & 31;
    const float* er = emb + w * 256;
    float s = 0.0f;
    #pragma unroll
    for (int k = 0; k < 8; k++) {
        int d = lane + (k << 5);
        s = fmaf(dec_w[d], er[d], s);
    }
    #pragma unroll
    for (int off = 16; off >= 1; off >>= 1)
        s += __shfl_down_sync(FULLM, s, off);
    if (lane == 0) g_score[w] = s;
}

// -------- kernel 2: per-interval line coefficients (direct sums) --------
__global__ void k_ab(const float* __restrict__ w1, const float* __restrict__ b1,
                     const float* __restrict__ w2, const float* __restrict__ b2)
{
    __shared__ float sw[NH], sb[NH];
    __shared__ int   sR[NH], sS[NH];
    int t = threadIdx.x;                 // 512 threads = code c
    int i = blockIdx.x;                  // interval 0..128
    if (t < NH) { sw[t] = w1[t]; sb[t] = b1[t]; sR[t] = g_actRank[t]; sS[t] = g_sgn[t]; }
    __syncthreads();
    float A = b2[t], Bv = 0.0f;
    const float* wr = w2 + t * NH;
    for (int j = 0; j < NH; j++) {
        bool act = (sS[j] > 0) ? (sR[j] < i) : (sR[j] >= i);
        if (act) {                       // warp-uniform predicate
            float v = wr[j];
            A  = fmaf(v, sb[j], A);
            Bv = fmaf(v, sw[j], Bv);
        }
    }
    g_A[i * NCODES + t] = A;
    g_B[i * NCODES + t] = Bv;
}

__device__ __forceinline__ int find_interval(const float* sk, float x) {
    int lo = 0, hi = NH;
    #pragma unroll
    for (int it = 0; it < 8; it++) {
        if (lo < hi) {
            int mid = (lo + hi) >> 1;
            if (sk[mid] <= x) lo = mid + 1; else hi = mid;
        }
    }
    return lo;   // number of kinks <= x, in [0,128]
}

// exact 512-line argmax from GLOBAL tables (fallback path only)
__device__ __forceinline__ void scan512(const float* __restrict__ Ar,
                                        const float* __restrict__ Br,
                                        float xv, int lane, int& out_idx)
{
    float best = neg_inf(); int bi = 0;
    #pragma unroll
    for (int k = 0; k < 16; k++) {
        int c = lane + (k << 5);
        float v = fmaf(Br[c], xv, Ar[c]);
        if (v > best) { best = v; bi = c; }        // ascending c -> first-max per lane
    }
    #pragma unroll
    for (int off = 16; off >= 1; off >>= 1) {
        float ov = __shfl_down_sync(FULLM, best, off);
        int   oi = __shfl_down_sync(FULLM, bi,  off);
        if (ov > best || (ov == best && oi < bi)) { best = ov; bi = oi; }
    }
    out_idx = __shfl_sync(FULLM, bi, 0);           // jnp.argmax first-index semantics
}

// -------- kernel 3: edge argmax, register-cached A/B, 16 edges per warp --------
__global__ void k_edges()
{
    __shared__ float sk[NH];
    int tid = threadIdx.x;
    if (tid < NH) sk[tid] = g_ksort[tid];
    __syncthreads();
    int wg = blockIdx.x * 8 + (tid >> 5);
    if (wg >= NEWARPS) return;
    int lane = tid & 31;
    int e0 = wg * 16;
    int cnt = min(16, NEDGES - e0);
    float xe0 = XMIN + (float)e0 * CW;
    int iv = find_interval(sk, xe0);
    float a[16], b[16];
    int iload = -1;
    for (int t = 0; t < cnt; t++) {
        float x = XMIN + (float)(e0 + t) * CW;
        while (iv < NH && sk[iv] <= x) iv++;       // warp-uniform, usually 0 iters
        if (iv != iload) {                         // coalesced reload, rare
            const float* Ar = g_A + iv * NCODES + lane;
            const float* Br = g_B + iv * NCODES + lane;
            #pragma unroll
            for (int k = 0; k < 16; k++) { a[k] = Ar[k << 5]; b[k] = Br[k << 5]; }
            iload = iv;
        }
        float best = neg_inf(); int bi = 0;
        #pragma unroll
        for (int k = 0; k < 16; k++) {
            float v = fmaf(b[k], x, a[k]);
            if (v > best) { best = v; bi = lane + (k << 5); }
        }
        #pragma unroll
        for (int off = 16; off >= 1; off >>= 1) {
            float ov = __shfl_down_sync(FULLM, best, off);
            int   oi = __shfl_down_sync(FULLM, bi,  off);
            if (ov > best || (ov == best && oi < bi)) { best = ov; bi = oi; }
        }
        if (lane == 0) g_edgeArg[e0 + t] = bi;
    }
}

// -------- kernel 3b: flag the 3 cells around each kink (set-only) --------
__global__ void k_flag()
{
    int t = threadIdx.x;                 // 128 threads
    float kv = g_ksort[t];
    if (!(kv >= XMIN - 2.0f * CW && kv < XMAX + 2.0f * CW)) return;  // also skips +inf
    int g = (int)floorf((kv - XMIN) * INV_CW);
    #pragma unroll
    for (int d = -1; d <= 1; d++) {
        int c = g + d;
        if (c >= 0 && c < NCELLS) g_kinkNear[c] = 1;
    }
}

// -------- kernel 4: classify cells --------
__global__ void k_cell()
{
    int g = blockIdx.x * blockDim.x + threadIdx.x;
    if (g >= NCELLS) return;
    int a0 = g_edgeArg[g];
    bool bad = (a0 != g_edgeArg[g + 1]) || g_kinkNear[g];
    g_cellInfo[g] = a0 | (bad ? (int)0x80000000 : 0);
}

// -------- kernel 5: per-element lookup + rare warp-aggregated fallback --------
__global__ void k_main(const float* __restrict__ x_in, float* __restrict__ out,
                       int n, int write_idx)
{
    __shared__ float sk[NH];
    if (threadIdx.x < NH) sk[threadIdx.x] = g_ksort[threadIdx.x];
    __syncthreads();
    int t = blockIdx.x * blockDim.x + threadIdx.x;
    int base = t * 4;
    bool active = base < n;
    bool full = active && (base + 3 < n);
    float xs[4] = {0.f, 0.f, 0.f, 0.f};
    if (full) {
        float4 xv = *(const float4*)(x_in + base);
        xs[0] = xv.x; xs[1] = xv.y; xs[2] = xv.z; xs[3] = xv.w;
    } else if (active) {
        for (int u = 0; u < 4 && base + u < n; u++) xs[u] = x_in[base + u];
    }
    int idx[4]; bool need[4];
    #pragma unroll
    for (int u = 0; u < 4; u++) {
        float x = xs[u];
        idx[u] = 0;
        need[u] = active && (base + u < n);
        if (need[u] && x >= XMIN && x < XMAX) {
            int g = (int)((x - XMIN) * INV_CW);
            if (g >= NCELLS) g = NCELLS - 1;
            int info = g_cellInfo[g];
            idx[u] = info & 0x7fffffff;
            need[u] = info < 0;
        }
    }
    int lane = threadIdx.x & 31;
    #pragma unroll
    for (int u = 0; u < 4; u++) {
        unsigned m = __ballot_sync(FULLM, need[u]);
        while (m) {                      // whole warp cooperates per fallback element
            int src = __ffs(m) - 1; m &= m - 1;
            float xb = __shfl_sync(FULLM, xs[u], src);
            int ib = find_interval(sk, xb);      // warp-uniform
            int bi;
            scan512(g_A + ib * NCODES, g_B + ib * NCODES, xb, lane, bi);
            if (lane == src) idx[u] = bi;
        }
    }
    if (!active) return;
    float db = g_decb;
    if (full) {
        float4 o;
        o.x = g_score[idx[0]] + db; o.y = g_score[idx[1]] + db;
        o.z = g_score[idx[2]] + db; o.w = g_score[idx[3]] + db;
        *(float4*)(out + base) = o;
        if (write_idx) {
            float4 oi = {(float)idx[0], (float)idx[1], (float)idx[2], (float)idx[3]};
            *(float4*)(out + n + base) = oi;
        }
    } else {
        for (int u = 0; u < 4 && base + u < n; u++) {
            out[base + u] = g_score[idx[u]] + db;
            if (write_idx) out[n + base + u] = (float)idx[u];
        }
    }
}

extern "C" void kernel_launch(void* const* d_in, const int* in_sizes, int n_in,
                              void* d_out, int out_size)
{
    const float* x     = (const float*)d_in[0];
    const float* w1    = (const float*)d_in[1];
    const float* b1    = (const float*)d_in[2];
    const float* w2    = (const float*)d_in[3];
    const float* b2    = (const float*)d_in[4];
    const float* emb   = (const float*)d_in[5];
    const float* dec_w = (const float*)d_in[6];
    const float* dec_b = (const float*)d_in[7];
    int n = in_sizes[0];
    float* out = (float*)d_out;

    k_setup<<<1, 128>>>(w1, b1, dec_b);
    k_score<<<128, 128>>>(emb, dec_w);
    k_ab<<<129, 512>>>(w1, b1, w2, b2);
    k_edges<<<(NEWARPS + 7) / 8, 256>>>();
    k_flag<<<1, 128>>>();
    k_cell<<<(NCELLS + 255) / 256, 256>>>();
    int write_idx = (out_size >= 2 * n) ? 1 : 0;
    int nthreads = (n + 3) / 4;
    k_main<<<(nthreads + 255) / 256, 256>>>(x, out, n, write_idx);
}